// round 1
// baseline (speedup 1.0000x reference)
#include <cuda_runtime.h>
#include <math.h>

#define NB   1024
#define NTOK 256
#define NV   200

// ---------------- device scratch (no allocations allowed) ----------------
__device__ float g_M[245];            // Mu[7][14] | Md[7][14] | Mp[7][7]
__device__ float g_udp[3][NB][NV];    // u, d, p attention outputs
__device__ float g_mean[3][NV];
__device__ float g_rstd[3][NV];
__device__ float g_part[4][NB];       // heads0..2, ego-net scalar per batch

// ---------------- helpers ----------------
__device__ __forceinline__ float warp_sum(float v) {
#pragma unroll
    for (int o = 16; o; o >>= 1) v += __shfl_xor_sync(0xffffffffu, v, o);
    return v;
}
__device__ __forceinline__ float warp_max(float v) {
#pragma unroll
    for (int o = 16; o; o >>= 1) v = fmaxf(v, __shfl_xor_sync(0xffffffffu, v, o));
    return v;
}

// ---------------- kernel 0: M = Wq @ Wk^T per attention ----------------
__global__ void k_precompute(const float* __restrict__ upWq, const float* __restrict__ upWk,
                             const float* __restrict__ dnWq, const float* __restrict__ dnWk,
                             const float* __restrict__ pvWq, const float* __restrict__ pvWk) {
    int t = threadIdx.x;
    if (t >= 245) return;
    const float *Wq, *Wk;
    int j, f;
    if (t < 98)       { Wq = upWq; Wk = upWk; j = t / 14;        f = t % 14; }
    else if (t < 196) { Wq = dnWq; Wk = dnWk; j = (t - 98) / 14; f = (t - 98) % 14; }
    else              { Wq = pvWq; Wk = pvWk; j = (t - 196) / 7; f = (t - 196) % 7; }
    float s = 0.f;
    for (int v = 0; v < NV; v++) s += Wq[j * NV + v] * Wk[f * NV + v];
    g_M[t] = s;
}

// ---------------- kernel 1: attention (1 block = 1 batch) ----------------
struct SRed {
    float wmax[8];
    float wsum[8];
    float wcnt[8];
    float wpart[8][14];
    float wf[14];
};

template <int F>
__device__ __forceinline__ void attend(const float* __restrict__ fr, const float* ego, bool mask,
                                       const float* sM, const float* __restrict__ Wv,
                                       float* __restrict__ outp, int t, SRed* red) {
    // qk = M^T @ ego (redundant per thread, trivial)
    float qk[F];
#pragma unroll
    for (int f = 0; f < F; f++) {
        float s = 0.f;
#pragma unroll
        for (int j = 0; j < 7; j++) s += ego[j] * sM[j * F + f];
        qk[f] = s;
    }
    // score for this token
    float sc = 0.f;
#pragma unroll
    for (int f = 0; f < F; f++) sc += fr[f] * qk[f];
    sc *= 0.07071067811865475f;  // 1/sqrt(200)
    float sval = mask ? sc : -1e9f;

    int wid = t >> 5, lane = t & 31;
    float m = warp_max(sval);
    if (lane == 0) red->wmax[wid] = m;
    __syncthreads();
    float bm = red->wmax[0];
#pragma unroll
    for (int w = 1; w < 8; w++) bm = fmaxf(bm, red->wmax[w]);

    float e  = __expf(sval - bm);
    float es = warp_sum(e);
    float cs = warp_sum(mask ? 1.f : 0.f);
    if (lane == 0) { red->wsum[wid] = es; red->wcnt[wid] = cs; }
    __syncthreads();
    float S = 0.f, C = 0.f;
#pragma unroll
    for (int w = 0; w < 8; w++) { S += red->wsum[w]; C += red->wcnt[w]; }
    float p = e / S;

    // weighted feature sum (F values, block reduce)
    float pf[F];
#pragma unroll
    for (int f = 0; f < F; f++) pf[f] = warp_sum(p * fr[f]);
    if (lane == 0) {
#pragma unroll
        for (int f = 0; f < F; f++) red->wpart[wid][f] = pf[f];
    }
    __syncthreads();
    if (t < F) {
        float s = 0.f;
#pragma unroll
        for (int w = 0; w < 8; w++) s += red->wpart[w][t];
        red->wf[t] = s;
    }
    __syncthreads();
    // out = wfeat @ Wv
    if (t < NV) {
        float o = 0.f;
        if (C > 0.5f) {
#pragma unroll
            for (int f = 0; f < F; f++) o += red->wf[f] * Wv[f * NV + t];
        }
        outp[t] = o;
    }
    __syncthreads();
}

__global__ __launch_bounds__(256) void k_attn(const float* __restrict__ merged,
                                              const float* __restrict__ a,
                                              const float* __restrict__ upWv,
                                              const float* __restrict__ dnWv,
                                              const float* __restrict__ pvWv) {
    __shared__ float feat[NTOK * 15];
    __shared__ float sM[245];
    __shared__ SRed red;
    int b = blockIdx.x, t = threadIdx.x;

    const float* src = merged + (size_t)b * NTOK * 15;
    for (int i = t; i < NTOK * 15; i += 256) feat[i] = src[i];
    if (t < 245) sM[t] = g_M[t];
    __syncthreads();

    float subj_id  = feat[0];
    float subj_loc = feat[2];
    __syncthreads();
    if (t == 0) feat[6] = a[b];      // merged[b,0,6] = a[b]
    feat[t * 15 + 0] -= subj_id;     // col 0 -= subj_id
    feat[t * 15 + 7] -= subj_id;     // col 7 -= subj_id
    __syncthreads();

    float ego[7];
#pragma unroll
    for (int j = 0; j < 7; j++) ego[j] = feat[j];

    const float* fr = feat + t * 15;
    float flag = fr[14], loc = fr[2];
    bool m_up = (loc < subj_loc) && (flag == 1.0f);
    bool m_dn = (loc > subj_loc) && (flag == 1.0f);
    bool m_pv = (flag == 0.0f);

    attend<14>(fr, ego, m_up, sM + 0,   upWv, &g_udp[0][b][0], t, &red);
    attend<14>(fr, ego, m_dn, sM + 98,  dnWv, &g_udp[1][b][0], t, &red);
    attend<7> (fr, ego, m_pv, sM + 196, pvWv, &g_udp[2][b][0], t, &red);
}

// ---------------- kernel 2: batch-norm stats over B ----------------
__global__ void k_stats() {
    int k  = blockIdx.y;
    int v  = blockIdx.x * 32 + threadIdx.x;
    int ty = threadIdx.y;
    double s = 0.0, s2 = 0.0;
    if (v < NV) {
        for (int b = ty; b < NB; b += 8) {
            float x = g_udp[k][b][v];
            s  += (double)x;
            s2 += (double)x * (double)x;
        }
    }
    __shared__ double ss[8][33], ss2[8][33];
    ss[ty][threadIdx.x]  = s;
    ss2[ty][threadIdx.x] = s2;
    __syncthreads();
    if (ty == 0 && v < NV) {
        for (int y = 1; y < 8; y++) { s += ss[y][threadIdx.x]; s2 += ss2[y][threadIdx.x]; }
        double mean = s / (double)NB;
        double var  = s2 / (double)NB - mean * mean;
        g_mean[k][v] = (float)mean;
        g_rstd[k][v] = (float)(1.0 / sqrt(var + 1e-5));
    }
}

// ---------------- kernel 3: 200x200 GEMMs (3 heads + ego net) ----------------
__global__ __launch_bounds__(256) void k_mlp(const float* __restrict__ merged,
                                             const float* __restrict__ a,
                                             const float* __restrict__ tW1,
                                             const float* __restrict__ tb1,
                                             const float* __restrict__ tW2,
                                             const float* __restrict__ tb2,
                                             const float* __restrict__ eW1,
                                             const float* __restrict__ eb1,
                                             const float* __restrict__ eW2,
                                             const float* __restrict__ eb2,
                                             const float* __restrict__ eW3,
                                             const float* __restrict__ eb3,
                                             const float* __restrict__ gamma,
                                             const float* __restrict__ beta) {
    int unit = blockIdx.y;       // 0..2 heads, 3 = ego net second layer
    int b0   = blockIdx.x * 32;
    int t    = threadIdx.x;

    __shared__ float X[32][NV];

    if (unit < 3) {
        for (int i = t; i < 32 * NV; i += 256) {
            int bb = i / NV, v = i % NV;
            float x = g_udp[unit][b0 + bb][v];
            X[bb][v] = gamma[v] * (x - g_mean[unit][v]) * g_rstd[unit][v] + beta[v];
        }
    } else {
        if (t < NV) {
            float w0 = eW1[0 * NV + t], w1 = eW1[1 * NV + t],
                  w2 = eW1[2 * NV + t], w3 = eW1[3 * NV + t];
            float bb1 = eb1[t];
            for (int bb = 0; bb < 32; bb++) {
                const float* mr = merged + (size_t)(b0 + bb) * NTOK * 15;
                float h = mr[3] * w0 + mr[4] * w1 + mr[5] * w2 + a[b0 + bb] * w3 + bb1;
                X[bb][t] = fmaxf(h, 0.f);
            }
        }
    }
    __syncthreads();

    const float* W    = (unit < 3) ? tW1 + unit * NV * NV : eW2;
    const float* bias = (unit < 3) ? tb1 + unit * NV : eb2;

    float acc[32];
    if (t < NV) {
        float bv = bias[t];
#pragma unroll
        for (int bb = 0; bb < 32; bb++) acc[bb] = bv;
        for (int v = 0; v < NV; v++) {
            float w = W[v * NV + t];
#pragma unroll
            for (int bb = 0; bb < 32; bb++) acc[bb] += X[bb][v] * w;
        }
        if (unit < 3) {
#pragma unroll
            for (int bb = 0; bb < 32; bb++)
                acc[bb] = acc[bb] > 0.f ? acc[bb] : expm1f(acc[bb]);   // elu
        } else {
#pragma unroll
            for (int bb = 0; bb < 32; bb++) acc[bb] = fmaxf(acc[bb], 0.f);  // relu
        }
        float w2 = (unit < 3) ? tW2[unit * NV + t] : eW3[t];
#pragma unroll
        for (int bb = 0; bb < 32; bb++) acc[bb] *= w2;
    } else {
#pragma unroll
        for (int bb = 0; bb < 32; bb++) acc[bb] = 0.f;
    }

    __shared__ float part[8][32];
#pragma unroll
    for (int bb = 0; bb < 32; bb++) {
        float v = warp_sum(acc[bb]);
        if ((t & 31) == 0) part[t >> 5][bb] = v;
    }
    __syncthreads();
    if (t < 32) {
        float s = 0.f;
#pragma unroll
        for (int w = 0; w < 8; w++) s += part[w][t];
        float fb = (unit < 3) ? tb2[unit] : eb3[0];
        g_part[unit][b0 + t] = s + fb;
    }
}

// ---------------- kernel 4: final sum ----------------
__global__ void k_final(float* __restrict__ out) {
    int b = blockIdx.x * 256 + threadIdx.x;
    if (b < NB)
        out[b] = g_part[0][b] + g_part[1][b] + g_part[2][b] + g_part[3][b];
}

// ---------------- launch ----------------
extern "C" void kernel_launch(void* const* d_in, const int* in_sizes, int n_in,
                              void* d_out, int out_size) {
    (void)in_sizes; (void)n_in; (void)out_size;
    const float* merged = (const float*)d_in[0];
    const float* a      = (const float*)d_in[1];
    const float* upWq   = (const float*)d_in[2];
    const float* upWk   = (const float*)d_in[3];
    const float* upWv   = (const float*)d_in[4];
    const float* dnWq   = (const float*)d_in[5];
    const float* dnWk   = (const float*)d_in[6];
    const float* dnWv   = (const float*)d_in[7];
    const float* pvWq   = (const float*)d_in[8];
    const float* pvWk   = (const float*)d_in[9];
    const float* pvWv   = (const float*)d_in[10];
    const float* tW1    = (const float*)d_in[11];
    const float* tb1    = (const float*)d_in[12];
    const float* tW2    = (const float*)d_in[13];
    const float* tb2    = (const float*)d_in[14];
    const float* eW1    = (const float*)d_in[15];
    const float* eb1    = (const float*)d_in[16];
    const float* eW2    = (const float*)d_in[17];
    const float* eb2    = (const float*)d_in[18];
    const float* eW3    = (const float*)d_in[19];
    const float* eb3    = (const float*)d_in[20];
    const float* gamma  = (const float*)d_in[21];
    const float* beta   = (const float*)d_in[22];
    float* out = (float*)d_out;

    k_precompute<<<1, 256>>>(upWq, upWk, dnWq, dnWk, pvWq, pvWk);
    k_attn<<<NB, 256>>>(merged, a, upWv, dnWv, pvWv);
    k_stats<<<dim3(7, 3), dim3(32, 8)>>>();
    k_mlp<<<dim3(NB / 32, 4), 256>>>(merged, a, tW1, tb1, tW2, tb2,
                                     eW1, eb1, eW2, eb2, eW3, eb3, gamma, beta);
    k_final<<<4, 256>>>(out);
}

// round 2
// speedup vs baseline: 1.2971x; 1.2971x over previous
#include <cuda_runtime.h>
#include <math.h>

#define NB   1024
#define NTOK 256
#define NV   200
#define KC   20          // W k-chunk rows staged in smem
#define NVP  224         // padded output dim (56 groups of 4)

// ---------------- device scratch ----------------
__device__ float g_M[245];            // Mu[7][14] | Md[7][14] | Mp[7][7]
__device__ float g_udp[3][NB][NV];    // u, d, p attention outputs
__device__ float g_mean[3][NV];
__device__ float g_rstd[3][NV];
__device__ float g_part[4][NB];       // heads0..2 + ego-net scalar per batch

// ---------------- helpers ----------------
__device__ __forceinline__ float warp_sum(float v) {
#pragma unroll
    for (int o = 16; o; o >>= 1) v += __shfl_xor_sync(0xffffffffu, v, o);
    return v;
}
__device__ __forceinline__ float warp_max(float v) {
#pragma unroll
    for (int o = 16; o; o >>= 1) v = fmaxf(v, __shfl_xor_sync(0xffffffffu, v, o));
    return v;
}

// ---------------- kernel 0: M = Wq @ Wk^T per attention ----------------
__global__ void k_precompute(const float* __restrict__ upWq, const float* __restrict__ upWk,
                             const float* __restrict__ dnWq, const float* __restrict__ dnWk,
                             const float* __restrict__ pvWq, const float* __restrict__ pvWk) {
    int t = threadIdx.x;
    if (t >= 245) return;
    const float *Wq, *Wk;
    int j, f;
    if (t < 98)       { Wq = upWq; Wk = upWk; j = t / 14;        f = t % 14; }
    else if (t < 196) { Wq = dnWq; Wk = dnWk; j = (t - 98) / 14; f = (t - 98) % 14; }
    else              { Wq = pvWq; Wk = pvWk; j = (t - 196) / 7; f = (t - 196) % 7; }
    float s = 0.f;
    for (int v = 0; v < NV; v++) s += Wq[j * NV + v] * Wk[f * NV + v];
    g_M[t] = s;
}

// ---------------- kernel 1: attention (1 block = 1 batch) ----------------
struct SRed {
    float wmax[8];
    float wsum[8];
    float wcnt[8];
    float wpart[8][14];
    float wf[14];
};

template <int F>
__device__ __forceinline__ void attend(const float* __restrict__ fr, const float* ego, bool mask,
                                       const float* sM, const float* __restrict__ Wv,
                                       float* __restrict__ outp, int t, SRed* red) {
    float qk[F];
#pragma unroll
    for (int f = 0; f < F; f++) {
        float s = 0.f;
#pragma unroll
        for (int j = 0; j < 7; j++) s += ego[j] * sM[j * F + f];
        qk[f] = s;
    }
    float sc = 0.f;
#pragma unroll
    for (int f = 0; f < F; f++) sc += fr[f] * qk[f];
    sc *= 0.07071067811865475f;  // 1/sqrt(200)
    float sval = mask ? sc : -1e9f;

    int wid = t >> 5, lane = t & 31;
    float m = warp_max(sval);
    if (lane == 0) red->wmax[wid] = m;
    __syncthreads();
    float bm = red->wmax[0];
#pragma unroll
    for (int w = 1; w < 8; w++) bm = fmaxf(bm, red->wmax[w]);

    float e  = __expf(sval - bm);
    float es = warp_sum(e);
    float cs = warp_sum(mask ? 1.f : 0.f);
    if (lane == 0) { red->wsum[wid] = es; red->wcnt[wid] = cs; }
    __syncthreads();
    float S = 0.f, C = 0.f;
#pragma unroll
    for (int w = 0; w < 8; w++) { S += red->wsum[w]; C += red->wcnt[w]; }
    float p = e / S;

    float pf[F];
#pragma unroll
    for (int f = 0; f < F; f++) pf[f] = warp_sum(p * fr[f]);
    if (lane == 0) {
#pragma unroll
        for (int f = 0; f < F; f++) red->wpart[wid][f] = pf[f];
    }
    __syncthreads();
    if (t < F) {
        float s = 0.f;
#pragma unroll
        for (int w = 0; w < 8; w++) s += red->wpart[w][t];
        red->wf[t] = s;
    }
    __syncthreads();
    if (t < NV) {
        float o = 0.f;
        if (C > 0.5f) {
#pragma unroll
            for (int f = 0; f < F; f++) o += red->wf[f] * Wv[f * NV + t];
        }
        outp[t] = o;
    }
    __syncthreads();
}

__global__ __launch_bounds__(256) void k_attn(const float* __restrict__ merged,
                                              const float* __restrict__ a,
                                              const float* __restrict__ upWv,
                                              const float* __restrict__ dnWv,
                                              const float* __restrict__ pvWv) {
    __shared__ float feat[NTOK * 15];
    __shared__ float sM[245];
    __shared__ SRed red;
    int b = blockIdx.x, t = threadIdx.x;

    const float* src = merged + (size_t)b * NTOK * 15;
    for (int i = t; i < NTOK * 15; i += 256) feat[i] = src[i];
    if (t < 245) sM[t] = g_M[t];
    __syncthreads();

    float subj_id  = feat[0];
    float subj_loc = feat[2];
    __syncthreads();
    if (t == 0) feat[6] = a[b];
    feat[t * 15 + 0] -= subj_id;
    feat[t * 15 + 7] -= subj_id;
    __syncthreads();

    float ego[7];
#pragma unroll
    for (int j = 0; j < 7; j++) ego[j] = feat[j];

    const float* fr = feat + t * 15;
    float flag = fr[14], loc = fr[2];
    bool m_up = (loc < subj_loc) && (flag == 1.0f);
    bool m_dn = (loc > subj_loc) && (flag == 1.0f);
    bool m_pv = (flag == 0.0f);

    attend<14>(fr, ego, m_up, sM + 0,   upWv, &g_udp[0][b][0], t, &red);
    attend<14>(fr, ego, m_dn, sM + 98,  dnWv, &g_udp[1][b][0], t, &red);
    attend<7> (fr, ego, m_pv, sM + 196, pvWv, &g_udp[2][b][0], t, &red);
}

// ---------------- kernel 2: batch-norm stats over B ----------------
__global__ void k_stats() {
    int k  = blockIdx.y;
    int v  = blockIdx.x * 32 + threadIdx.x;
    int ty = threadIdx.y;
    double s = 0.0, s2 = 0.0;
    if (v < NV) {
        for (int b = ty; b < NB; b += 8) {
            float x = g_udp[k][b][v];
            s  += (double)x;
            s2 += (double)x * (double)x;
        }
    }
    __shared__ double ss[8][33], ss2[8][33];
    ss[ty][threadIdx.x]  = s;
    ss2[ty][threadIdx.x] = s2;
    __syncthreads();
    if (ty == 0 && v < NV) {
        for (int y = 1; y < 8; y++) { s += ss[y][threadIdx.x]; s2 += ss2[y][threadIdx.x]; }
        double mean = s / (double)NB;
        double var  = s2 / (double)NB - mean * mean;
        g_mean[k][v] = (float)mean;
        g_rstd[k][v] = (float)(1.0 / sqrt(var + 1e-5));
    }
}

// ---------------- kernel 3: 200x200 GEMMs, 2-D register tiled ----------------
// Block: 32 batches x 200 outputs (padded to 224). 256 threads.
// Thread (ty = t>>6 in 0..3, tx = t&63, active when tx<56):
//   micro-tile = batches [ty*8, ty*8+8) x outputs [tx*4, tx*4+4).
// Per k-step: 8 broadcast LDS (X) + 1 LDS.128 (W) + 32 FFMA  -> FMA-bound.
__global__ __launch_bounds__(256) void k_mlp(const float* __restrict__ merged,
                                             const float* __restrict__ a,
                                             const float* __restrict__ tW1,
                                             const float* __restrict__ tb1,
                                             const float* __restrict__ tW2,
                                             const float* __restrict__ tb2,
                                             const float* __restrict__ eW1,
                                             const float* __restrict__ eb1,
                                             const float* __restrict__ eW2,
                                             const float* __restrict__ eb2,
                                             const float* __restrict__ eW3,
                                             const float* __restrict__ eb3,
                                             const float* __restrict__ gamma,
                                             const float* __restrict__ beta) {
    int unit = blockIdx.y;       // 0..2 heads, 3 = ego net
    int b0   = blockIdx.x * 32;
    int t    = threadIdx.x;
    int ty   = t >> 6;           // 0..3  (batch group, warp-uniform)
    int tx   = t & 63;           // 0..63 (output group; active < 56)
    bool act = tx < 56;

    __shared__ float X[32][NV];       // activations  (25600 B)
    __shared__ float Ws[KC][NVP];     // W chunk      (17920 B)

    // ---- build X ----
    if (unit < 3) {
        for (int i = t; i < 32 * NV; i += 256) {
            int bb = i / NV, v = i - bb * NV;
            float x = g_udp[unit][b0 + bb][v];
            X[bb][v] = gamma[v] * (x - g_mean[unit][v]) * g_rstd[unit][v] + beta[v];
        }
    } else {
        if (t < NV) {
            float w0 = eW1[0 * NV + t], w1 = eW1[1 * NV + t],
                  w2 = eW1[2 * NV + t], w3 = eW1[3 * NV + t];
            float bb1 = eb1[t];
            for (int bb = 0; bb < 32; bb++) {
                const float* mr = merged + (size_t)(b0 + bb) * NTOK * 15;
                float h = mr[3] * w0 + mr[4] * w1 + mr[5] * w2 + a[b0 + bb] * w3 + bb1;
                X[bb][t] = fmaxf(h, 0.f);
            }
        }
    }
    // zero W padding columns once (never overwritten by chunk loads)
    for (int i = t; i < KC * (NVP - NV); i += 256) {
        int kc = i / (NVP - NV), o = i - kc * (NVP - NV);
        Ws[kc][NV + o] = 0.f;
    }

    const float* Wg   = (unit < 3) ? tW1 + (size_t)unit * NV * NV : eW2;
    const float* bias = (unit < 3) ? tb1 + unit * NV : eb2;

    // ---- init accumulators with bias ----
    float acc[8][4];
    {
        int o0 = tx * 4;
        float b4[4];
#pragma unroll
        for (int j = 0; j < 4; j++)
            b4[j] = (act && o0 + j < NV) ? bias[o0 + j] : 0.f;
#pragma unroll
        for (int i = 0; i < 8; i++)
#pragma unroll
            for (int j = 0; j < 4; j++) acc[i][j] = b4[j];
    }

    // ---- main loop: stream W in KC-row chunks ----
    for (int k0 = 0; k0 < NV; k0 += KC) {
        __syncthreads();
        for (int i = t; i < KC * NV; i += 256) {
            int kc = i / NV, o = i - kc * NV;
            Ws[kc][o] = Wg[(size_t)(k0 + kc) * NV + o];
        }
        __syncthreads();
        if (act) {
#pragma unroll
            for (int kc = 0; kc < KC; kc++) {
                float4 w = *reinterpret_cast<const float4*>(&Ws[kc][tx * 4]);
                float xv[8];
#pragma unroll
                for (int i = 0; i < 8; i++) xv[i] = X[ty * 8 + i][k0 + kc];
#pragma unroll
                for (int i = 0; i < 8; i++) {
                    acc[i][0] = fmaf(xv[i], w.x, acc[i][0]);
                    acc[i][1] = fmaf(xv[i], w.y, acc[i][1]);
                    acc[i][2] = fmaf(xv[i], w.z, acc[i][2]);
                    acc[i][3] = fmaf(xv[i], w.w, acc[i][3]);
                }
            }
        }
    }

    // ---- epilogue: activation, *W2, partial sums ----
    float* red = &X[0][0];   // reuse: red[56][33]
    float p[8];
    {
        int o0 = tx * 4;
        float w2v[4];
#pragma unroll
        for (int j = 0; j < 4; j++) {
            int o = o0 + j;
            float w2 = 0.f;
            if (act && o < NV) w2 = (unit < 3) ? tW2[unit * NV + o] : eW3[o];
            w2v[j] = w2;
        }
#pragma unroll
        for (int i = 0; i < 8; i++) {
            float s = 0.f;
#pragma unroll
            for (int j = 0; j < 4; j++) {
                float v = acc[i][j];
                v = (unit < 3) ? (v > 0.f ? v : expm1f(v))   // elu
                               : fmaxf(v, 0.f);              // relu
                s = fmaf(v, w2v[j], s);
            }
            p[i] = s;
        }
    }
    __syncthreads();   // done reading X
    if (act) {
#pragma unroll
        for (int i = 0; i < 8; i++) red[tx * 33 + ty * 8 + i] = p[i];
    }
    __syncthreads();
    if (t < 32) {
        float s = 0.f;
        for (int j = 0; j < 56; j++) s += red[j * 33 + t];
        float fb = (unit < 3) ? tb2[unit] : eb3[0];
        g_part[unit][b0 + t] = s + fb;
    }
}

// ---------------- kernel 4: final sum ----------------
__global__ void k_final(float* __restrict__ out) {
    int b = blockIdx.x * 256 + threadIdx.x;
    if (b < NB)
        out[b] = g_part[0][b] + g_part[1][b] + g_part[2][b] + g_part[3][b];
}

// ---------------- launch ----------------
extern "C" void kernel_launch(void* const* d_in, const int* in_sizes, int n_in,
                              void* d_out, int out_size) {
    (void)in_sizes; (void)n_in; (void)out_size;
    const float* merged = (const float*)d_in[0];
    const float* a      = (const float*)d_in[1];
    const float* upWq   = (const float*)d_in[2];
    const float* upWk   = (const float*)d_in[3];
    const float* upWv   = (const float*)d_in[4];
    const float* dnWq   = (const float*)d_in[5];
    const float* dnWk   = (const float*)d_in[6];
    const float* dnWv   = (const float*)d_in[7];
    const float* pvWq   = (const float*)d_in[8];
    const float* pvWk   = (const float*)d_in[9];
    const float* pvWv   = (const float*)d_in[10];
    const float* tW1    = (const float*)d_in[11];
    const float* tb1    = (const float*)d_in[12];
    const float* tW2    = (const float*)d_in[13];
    const float* tb2    = (const float*)d_in[14];
    const float* eW1    = (const float*)d_in[15];
    const float* eb1    = (const float*)d_in[16];
    const float* eW2    = (const float*)d_in[17];
    const float* eb2    = (const float*)d_in[18];
    const float* eW3    = (const float*)d_in[19];
    const float* eb3    = (const float*)d_in[20];
    const float* gamma  = (const float*)d_in[21];
    const float* beta   = (const float*)d_in[22];
    float* out = (float*)d_out;

    k_precompute<<<1, 256>>>(upWq, upWk, dnWq, dnWk, pvWq, pvWk);
    k_attn<<<NB, 256>>>(merged, a, upWv, dnWv, pvWv);
    k_stats<<<dim3(7, 3), dim3(32, 8)>>>();
    k_mlp<<<dim3(NB / 32, 4), 256>>>(merged, a, tW1, tb1, tW2, tb2,
                                     eW1, eb1, eW2, eb2, eW3, eb3, gamma, beta);
    k_final<<<4, 256>>>(out);
}

// round 3
// speedup vs baseline: 1.4056x; 1.0836x over previous
#include <cuda_runtime.h>
#include <math.h>

#define NB   1024
#define NTOK 256
#define NV   200
#define KC   25          // W k-chunk rows staged in smem
#define NVP  224         // padded output dim (56 groups of 4)
#define BT   16          // batch tile in k_mlp

typedef unsigned long long u64;

// ---------------- device scratch ----------------
__device__ float g_udp[3][NB][NV];    // u, d, p attention outputs
__device__ float g_mean[3][NV];
__device__ float g_rstd[3][NV];
__device__ float g_part[4][NB];

// ---------------- helpers ----------------
__device__ __forceinline__ float warp_sum(float v) {
#pragma unroll
    for (int o = 16; o; o >>= 1) v += __shfl_xor_sync(0xffffffffu, v, o);
    return v;
}
__device__ __forceinline__ float warp_max(float v) {
#pragma unroll
    for (int o = 16; o; o >>= 1) v = fmaxf(v, __shfl_xor_sync(0xffffffffu, v, o));
    return v;
}
__device__ __forceinline__ u64 ffma2(u64 a, u64 b, u64 c) {
    u64 d;
    asm("fma.rn.f32x2 %0, %1, %2, %3;" : "=l"(d) : "l"(a), "l"(b), "l"(c));
    return d;
}
union F2U { float2 f; u64 u; };
__device__ __forceinline__ u64 pack2(float x, float y) {
    F2U t; t.f = make_float2(x, y); return t.u;
}
__device__ __forceinline__ float2 unpack2(u64 v) { F2U t; t.u = v; return t.f; }

// ---------------- kernel 1: attention, warp-per-batch ----------------
__global__ __launch_bounds__(256) void k_attn(const float* __restrict__ merged,
                                              const float* __restrict__ a,
                                              const float* __restrict__ upWq, const float* __restrict__ upWk,
                                              const float* __restrict__ upWv,
                                              const float* __restrict__ dnWq, const float* __restrict__ dnWk,
                                              const float* __restrict__ dnWv,
                                              const float* __restrict__ pvWq, const float* __restrict__ pvWk,
                                              const float* __restrict__ pvWv) {
    __shared__ float sWv[35 * NV];   // up[14] | dn[14] | pv[7] rows of 200
    __shared__ float sM[245];        // Mu[7][14] | Md[7][14] | Mp[7][7]
    int t = threadIdx.x;

    // stage Wv matrices
    for (int i = t; i < 14 * NV; i += 256) sWv[i] = upWv[i];
    for (int i = t; i < 14 * NV; i += 256) sWv[2800 + i] = dnWv[i];
    for (int i = t; i < 7 * NV;  i += 256) sWv[5600 + i] = pvWv[i];
    // M = Wq @ Wk^T (tiny, float4 dot)
    if (t < 245) {
        const float *Wq, *Wk; int j, f;
        if (t < 98)       { Wq = upWq; Wk = upWk; j = t / 14;        f = t % 14; }
        else if (t < 196) { Wq = dnWq; Wk = dnWk; j = (t - 98) / 14; f = (t - 98) % 14; }
        else              { Wq = pvWq; Wk = pvWk; j = (t - 196) / 7; f = (t - 196) % 7; }
        const float4* q4 = (const float4*)(Wq + j * NV);
        const float4* k4 = (const float4*)(Wk + f * NV);
        float s = 0.f;
#pragma unroll 5
        for (int v = 0; v < NV / 4; v++) {
            float4 qa = q4[v], ka = k4[v];
            s += qa.x * ka.x + qa.y * ka.y + qa.z * ka.z + qa.w * ka.w;
        }
        sM[t] = s;
    }
    __syncthreads();

    int warp = t >> 5, lane = t & 31;
    int b = blockIdx.x * 8 + warp;
    const float* src = merged + (size_t)b * NTOK * 15;
    float a_b = a[b];
    float subj_id = src[0], subj_loc = src[2];

    // ego (after updates): [0, m1..m5, a]
    float ego[7];
    ego[0] = 0.f; ego[1] = src[1]; ego[2] = src[2]; ego[3] = src[3];
    ego[4] = src[4]; ego[5] = src[5]; ego[6] = a_b;

    // qk = M^T @ ego
    float qku[14], qkd[14], qkp[7];
#pragma unroll
    for (int f = 0; f < 14; f++) {
        float s1 = 0.f, s2 = 0.f;
#pragma unroll
        for (int j = 0; j < 7; j++) {
            s1 += ego[j] * sM[j * 14 + f];
            s2 += ego[j] * sM[98 + j * 14 + f];
        }
        qku[f] = s1; qkd[f] = s2;
    }
#pragma unroll
    for (int f = 0; f < 7; f++) {
        float s3 = 0.f;
#pragma unroll
        for (int j = 0; j < 7; j++) s3 += ego[j] * sM[196 + j * 7 + f];
        qkp[f] = s3;
    }

    const float scale = 0.07071067811865475f;
    float su[8], sd[8], sp[8];
    float cu = 0.f, cd = 0.f, cp = 0.f;

    // pass 1: scores
#pragma unroll
    for (int j = 0; j < 8; j++) {
        int tk = lane + 32 * j;
        const float* fr = src + tk * 15;
        float f[15];
#pragma unroll
        for (int q = 0; q < 15; q++) f[q] = fr[q];
        f[0] -= subj_id; f[7] -= subj_id;
        if (tk == 0) f[6] = a_b;
        float s1 = 0.f, s2 = 0.f, s3 = 0.f;
#pragma unroll
        for (int q = 0; q < 14; q++) { s1 += f[q] * qku[q]; s2 += f[q] * qkd[q]; }
#pragma unroll
        for (int q = 0; q < 7; q++)  s3 += f[q] * qkp[q];
        bool fl1 = (f[14] == 1.0f);
        bool m_up = (f[2] < subj_loc) && fl1;
        bool m_dn = (f[2] > subj_loc) && fl1;
        bool m_pv = (f[14] == 0.0f);
        su[j] = m_up ? s1 * scale : -1e9f;
        sd[j] = m_dn ? s2 * scale : -1e9f;
        sp[j] = m_pv ? s3 * scale : -1e9f;
        cu += m_up ? 1.f : 0.f; cd += m_dn ? 1.f : 0.f; cp += m_pv ? 1.f : 0.f;
    }

    float mu = su[0], md = sd[0], mp = sp[0];
#pragma unroll
    for (int j = 1; j < 8; j++) {
        mu = fmaxf(mu, su[j]); md = fmaxf(md, sd[j]); mp = fmaxf(mp, sp[j]);
    }
    mu = warp_max(mu); md = warp_max(md); mp = warp_max(mp);

    float Su = 0.f, Sd = 0.f, Sp = 0.f;
#pragma unroll
    for (int j = 0; j < 8; j++) {
        su[j] = __expf(su[j] - mu); Su += su[j];
        sd[j] = __expf(sd[j] - md); Sd += sd[j];
        sp[j] = __expf(sp[j] - mp); Sp += sp[j];
    }
    Su = warp_sum(Su); Sd = warp_sum(Sd); Sp = warp_sum(Sp);
    cu = warp_sum(cu); cd = warp_sum(cd); cp = warp_sum(cp);

    // pass 2: weighted feature sums (unnormalized)
    float wfu[14], wfd[14], wfp[7];
#pragma unroll
    for (int q = 0; q < 14; q++) { wfu[q] = 0.f; wfd[q] = 0.f; }
#pragma unroll
    for (int q = 0; q < 7; q++)  wfp[q] = 0.f;
#pragma unroll
    for (int j = 0; j < 8; j++) {
        int tk = lane + 32 * j;
        const float* fr = src + tk * 15;
        float f[14];
#pragma unroll
        for (int q = 0; q < 14; q++) f[q] = fr[q];
        f[0] -= subj_id; f[7] -= subj_id;
        if (tk == 0) f[6] = a_b;
        float eu = su[j], ed = sd[j], ep = sp[j];
#pragma unroll
        for (int q = 0; q < 14; q++) {
            wfu[q] = fmaf(eu, f[q], wfu[q]);
            wfd[q] = fmaf(ed, f[q], wfd[q]);
        }
#pragma unroll
        for (int q = 0; q < 7; q++) wfp[q] = fmaf(ep, f[q], wfp[q]);
    }
#pragma unroll
    for (int q = 0; q < 14; q++) { wfu[q] = warp_sum(wfu[q]); wfd[q] = warp_sum(wfd[q]); }
#pragma unroll
    for (int q = 0; q < 7; q++)  wfp[q] = warp_sum(wfp[q]);

    float iSu = (cu > 0.5f) ? 1.f / Su : 0.f;
    float iSd = (cd > 0.5f) ? 1.f / Sd : 0.f;
    float iSp = (cp > 0.5f) ? 1.f / Sp : 0.f;

    // out = (wf/S) @ Wv
    for (int o = lane; o < NV; o += 32) {
        float ou = 0.f, od = 0.f, op = 0.f;
#pragma unroll
        for (int q = 0; q < 14; q++) {
            ou = fmaf(wfu[q], sWv[q * NV + o], ou);
            od = fmaf(wfd[q], sWv[2800 + q * NV + o], od);
        }
#pragma unroll
        for (int q = 0; q < 7; q++) op = fmaf(wfp[q], sWv[5600 + q * NV + o], op);
        g_udp[0][b][o] = ou * iSu;
        g_udp[1][b][o] = od * iSd;
        g_udp[2][b][o] = op * iSp;
    }
}

// ---------------- kernel 2: batch-norm stats ----------------
__global__ void k_stats() {
    int k  = blockIdx.y;
    int v  = blockIdx.x * 32 + threadIdx.x;
    int ty = threadIdx.y;           // 0..31
    double s = 0.0, s2 = 0.0;
    if (v < NV) {
        for (int b = ty; b < NB; b += 32) {
            float x = g_udp[k][b][v];
            s  += (double)x;
            s2 += (double)x * (double)x;
        }
    }
    __shared__ double ss[32][33], ss2[32][33];
    ss[ty][threadIdx.x]  = s;
    ss2[ty][threadIdx.x] = s2;
    __syncthreads();
    if (ty == 0 && v < NV) {
        for (int y = 1; y < 32; y++) { s += ss[y][threadIdx.x]; s2 += ss2[y][threadIdx.x]; }
        double mean = s / (double)NB;
        double var  = s2 / (double)NB - mean * mean;
        g_mean[k][v] = (float)mean;
        g_rstd[k][v] = (float)(1.0 / sqrt(var + 1e-5));
    }
}

// ---------------- kernel 3: 200x200 GEMMs, f32x2 packed ----------------
// Block: 16 batches x 200 outputs (padded 224), 256 threads.
// ty = t>>6 (0..3): 4 batches each; tx = t&63 (active<56): 4 outputs.
// acc: 4 batches x 2 f32x2 pairs. Per k: 1 LDS.128(W) + 4 LDS.64(X dup) + 8 FFMA2.
__global__ __launch_bounds__(256) void k_mlp(const float* __restrict__ merged,
                                             const float* __restrict__ a,
                                             const float* __restrict__ tW1,
                                             const float* __restrict__ tb1,
                                             const float* __restrict__ tW2,
                                             const float* __restrict__ tb2,
                                             const float* __restrict__ eW1,
                                             const float* __restrict__ eb1,
                                             const float* __restrict__ eW2,
                                             const float* __restrict__ eb2,
                                             const float* __restrict__ eW3,
                                             const float* __restrict__ eb3,
                                             const float* __restrict__ gamma,
                                             const float* __restrict__ beta) {
    int unit = blockIdx.y;        // 0..2 heads, 3 = ego net
    int b0   = blockIdx.x * BT;
    int t    = threadIdx.x;
    int ty   = t >> 6;            // 0..3 (warp-uniform)
    int tx   = t & 63;            // 0..63, active < 56
    bool act = tx < 56;

    __shared__ float2 Xd[BT][NV];   // duplicated activations (25600 B)
    __shared__ float  Ws[KC][NVP];  // W chunk (22400 B)

    // ---- build X (duplicated) ----
    if (unit < 3) {
        for (int i = t; i < BT * NV; i += 256) {
            int bb = i / NV, v = i - bb * NV;
            float x = g_udp[unit][b0 + bb][v];
            x = gamma[v] * (x - g_mean[unit][v]) * g_rstd[unit][v] + beta[v];
            Xd[bb][v] = make_float2(x, x);
        }
    } else if (t < NV) {
        float w0 = eW1[t], w1 = eW1[NV + t], w2 = eW1[2 * NV + t], w3 = eW1[3 * NV + t];
        float bb1 = eb1[t];
        for (int bb = 0; bb < BT; bb++) {
            const float* mr = merged + (size_t)(b0 + bb) * NTOK * 15;
            float h = fmaxf(mr[3] * w0 + mr[4] * w1 + mr[5] * w2 + a[b0 + bb] * w3 + bb1, 0.f);
            Xd[bb][t] = make_float2(h, h);
        }
    }
    // zero W padding columns (written once, never overwritten)
    for (int i = t; i < KC * (NVP - NV); i += 256) {
        int kc = i / (NVP - NV), o = i - kc * (NVP - NV);
        Ws[kc][NV + o] = 0.f;
    }

    const float* Wg   = (unit < 3) ? tW1 + (size_t)unit * NV * NV : eW2;
    const float* bias = (unit < 3) ? tb1 + unit * NV : eb2;

    int o0 = tx * 4;
    u64 acc[4][2];
    {
        float bj[4];
#pragma unroll
        for (int j = 0; j < 4; j++) bj[j] = (act && o0 + j < NV) ? bias[o0 + j] : 0.f;
#pragma unroll
        for (int i = 0; i < 4; i++) {
            acc[i][0] = pack2(bj[0], bj[1]);
            acc[i][1] = pack2(bj[2], bj[3]);
        }
    }

    // ---- main loop ----
    for (int k0 = 0; k0 < NV; k0 += KC) {
        __syncthreads();
        for (int i = t; i < KC * NV; i += 256) {
            int kc = i / NV, o = i - kc * NV;
            Ws[kc][o] = Wg[(size_t)(k0 + kc) * NV + o];
        }
        __syncthreads();
        if (act) {
#pragma unroll 5
            for (int kc = 0; kc < KC; kc++) {
                ulonglong2 w = *reinterpret_cast<const ulonglong2*>(&Ws[kc][o0]);
                u64 x0 = *reinterpret_cast<const u64*>(&Xd[ty * 4 + 0][k0 + kc]);
                u64 x1 = *reinterpret_cast<const u64*>(&Xd[ty * 4 + 1][k0 + kc]);
                u64 x2 = *reinterpret_cast<const u64*>(&Xd[ty * 4 + 2][k0 + kc]);
                u64 x3 = *reinterpret_cast<const u64*>(&Xd[ty * 4 + 3][k0 + kc]);
                acc[0][0] = ffma2(x0, w.x, acc[0][0]); acc[0][1] = ffma2(x0, w.y, acc[0][1]);
                acc[1][0] = ffma2(x1, w.x, acc[1][0]); acc[1][1] = ffma2(x1, w.y, acc[1][1]);
                acc[2][0] = ffma2(x2, w.x, acc[2][0]); acc[2][1] = ffma2(x2, w.y, acc[2][1]);
                acc[3][0] = ffma2(x3, w.x, acc[3][0]); acc[3][1] = ffma2(x3, w.y, acc[3][1]);
            }
        }
    }

    // ---- epilogue: activation, *W2, reduce ----
    float w2v[4];
#pragma unroll
    for (int j = 0; j < 4; j++) {
        int o = o0 + j;
        w2v[j] = (act && o < NV) ? ((unit < 3) ? tW2[unit * NV + o] : eW3[o]) : 0.f;
    }
    float p[4];
#pragma unroll
    for (int i = 0; i < 4; i++) {
        float2 v01 = unpack2(acc[i][0]);
        float2 v23 = unpack2(acc[i][1]);
        float v[4] = {v01.x, v01.y, v23.x, v23.y};
        float s = 0.f;
#pragma unroll
        for (int j = 0; j < 4; j++) {
            float x = v[j];
            x = (unit < 3) ? (x > 0.f ? x : expm1f(x)) : fmaxf(x, 0.f);
            s = fmaf(x, w2v[j], s);
        }
        p[i] = s;
    }
    __syncthreads();                       // done reading Xd
    float* red = (float*)&Xd[0][0];        // red[56][17]
    if (act) {
#pragma unroll
        for (int i = 0; i < 4; i++) red[tx * 17 + ty * 4 + i] = p[i];
    }
    __syncthreads();
    if (t < BT) {
        float s = 0.f;
        for (int j = 0; j < 56; j++) s += red[j * 17 + t];
        float fb = (unit < 3) ? tb2[unit] : eb3[0];
        g_part[unit][b0 + t] = s + fb;
    }
}

// ---------------- kernel 4: final sum ----------------
__global__ void k_final(float* __restrict__ out) {
    int b = blockIdx.x * 256 + threadIdx.x;
    if (b < NB)
        out[b] = g_part[0][b] + g_part[1][b] + g_part[2][b] + g_part[3][b];
}

// ---------------- launch ----------------
extern "C" void kernel_launch(void* const* d_in, const int* in_sizes, int n_in,
                              void* d_out, int out_size) {
    (void)in_sizes; (void)n_in; (void)out_size;
    const float* merged = (const float*)d_in[0];
    const float* a      = (const float*)d_in[1];
    const float* upWq   = (const float*)d_in[2];
    const float* upWk   = (const float*)d_in[3];
    const float* upWv   = (const float*)d_in[4];
    const float* dnWq   = (const float*)d_in[5];
    const float* dnWk   = (const float*)d_in[6];
    const float* dnWv   = (const float*)d_in[7];
    const float* pvWq   = (const float*)d_in[8];
    const float* pvWk   = (const float*)d_in[9];
    const float* pvWv   = (const float*)d_in[10];
    const float* tW1    = (const float*)d_in[11];
    const float* tb1    = (const float*)d_in[12];
    const float* tW2    = (const float*)d_in[13];
    const float* tb2    = (const float*)d_in[14];
    const float* eW1    = (const float*)d_in[15];
    const float* eb1    = (const float*)d_in[16];
    const float* eW2    = (const float*)d_in[17];
    const float* eb2    = (const float*)d_in[18];
    const float* eW3    = (const float*)d_in[19];
    const float* eb3    = (const float*)d_in[20];
    const float* gamma  = (const float*)d_in[21];
    const float* beta   = (const float*)d_in[22];
    float* out = (float*)d_out;

    k_attn<<<NB / 8, 256>>>(merged, a, upWq, upWk, upWv, dnWq, dnWk, dnWv,
                            pvWq, pvWk, pvWv);
    k_stats<<<dim3(7, 3), dim3(32, 32)>>>();
    k_mlp<<<dim3(NB / BT, 4), 256>>>(merged, a, tW1, tb1, tW2, tb2,
                                     eW1, eb1, eW2, eb2, eW3, eb3, gamma, beta);
    k_final<<<4, 256>>>(out);
}